// round 1
// baseline (speedup 1.0000x reference)
#include <cuda_runtime.h>
#include <math.h>

#define T_MAX  4096
#define D_MODEL 1024
#define HID    4096
#define NE     8

// ---------------- device scratch (static globals: no allocations) ----------
__device__ float         g_gates[T_MAX * 2];        // top-2 softmaxed gate values
__device__ int           g_topk [T_MAX * 2];        // top-2 expert ids
__device__ int           g_counts[NE];              // tokens routed per expert
__device__ int           g_tok   [(NE + 1) * T_MAX];   // row -> token (seg s at s*T_MAX)
__device__ float         g_rowgate[(NE + 1) * T_MAX];  // row -> gate value
__device__ unsigned char g_rowslot[(NE + 1) * T_MAX];  // row -> slot (0/1)
__device__ float         g_H[(size_t)(NE + 1) * T_MAX * HID];      // hidden acts (~604MB)
__device__ float         g_slotbuf[(size_t)2 * T_MAX * D_MODEL];   // per-slot expert outputs

// ---------------- gating: logits -> top2 -> softmax ------------------------
__global__ void gate_kernel(const float* __restrict__ x,
                            const float* __restrict__ gw, int T) {
    int warp = (blockIdx.x * blockDim.x + threadIdx.x) >> 5;
    int lane = threadIdx.x & 31;
    if (warp >= T) return;
    const float* xr = x + (size_t)warp * D_MODEL;
    float logit[NE];
#pragma unroll
    for (int e = 0; e < NE; e++) {
        float s = 0.f;
        for (int k = lane; k < D_MODEL; k += 32)
            s = fmaf(xr[k], gw[e * D_MODEL + k], s);
#pragma unroll
        for (int o = 16; o; o >>= 1) s += __shfl_xor_sync(0xffffffffu, s, o);
        logit[e] = s;
    }
    if (lane == 0) {
        int i0 = 0; float v0 = logit[0];
#pragma unroll
        for (int e = 1; e < NE; e++) if (logit[e] > v0) { v0 = logit[e]; i0 = e; }
        int i1 = -1; float v1 = -1e30f;
#pragma unroll
        for (int e = 0; e < NE; e++) if (e != i0 && logit[e] > v1) { v1 = logit[e]; i1 = e; }
        float e1  = expf(v1 - v0);          // stable: exp(v0-v0)=1
        float inv = 1.f / (1.f + e1);
        g_topk [2 * warp]     = i0;
        g_topk [2 * warp + 1] = i1;
        g_gates[2 * warp]     = inv;
        g_gates[2 * warp + 1] = e1 * inv;
    }
}

// ---------------- deterministic routing (per-expert prefix scan) -----------
__global__ void route_kernel(int T) {
    int e   = blockIdx.x;
    int tid = threadIdx.x, lane = tid & 31, wid = tid >> 5;
    if (e == NE) {  // fill the "shared expert" segment (identity routing)
        for (int i = tid; i < T; i += blockDim.x) {
            g_tok[i] = i; g_rowgate[i] = 1.f; g_rowslot[i] = 0;
        }
        return;
    }
    __shared__ int wsum[8], wpre[8], s_total;
    int base = 0;
    for (int t0 = 0; t0 < T; t0 += 256) {
        int t = t0 + tid;
        int slot = -1;
        if (t < T) {
            if      (g_topk[2 * t]     == e) slot = 0;
            else if (g_topk[2 * t + 1] == e) slot = 1;
        }
        unsigned m = __ballot_sync(0xffffffffu, slot >= 0);
        int pre = __popc(m & ((1u << lane) - 1u));
        if (lane == 0) wsum[wid] = __popc(m);
        __syncthreads();
        if (tid == 0) {
            int a = 0;
            for (int w = 0; w < 8; w++) { wpre[w] = a; a += wsum[w]; }
            s_total = a;
        }
        __syncthreads();
        if (slot >= 0) {
            int pos = base + wpre[wid] + pre;
            size_t r = (size_t)(e + 1) * T_MAX + pos;
            g_tok[r]     = t;
            g_rowgate[r] = g_gates[2 * t + slot];
            g_rowslot[r] = (unsigned char)slot;
        }
        base += s_total;
        __syncthreads();
    }
    if (tid == 0) g_counts[e] = base;
}

// ---------------- tiled fp32 GEMM, 128x128x16, 256 threads, 8x8/thread -----
// STAGE 1: H[r,:] = silu( X[tok(r),:] @ W1_s^T )   (K=1024, N=4096)
// STAGE 2: Y[r,:] = H[r,:] @ W2_s^T                (K=4096, N=1024)
//   OUTMODE 0: out[tok,:] = g*Y  (shared expert, writes every element)
//   OUTMODE 1: slotbuf[slot,tok,:] = g*Y (routed experts, race-free)
template <int STAGE, int OUTMODE>
__global__ void __launch_bounds__(256, 2)
gemm_kernel(const float* __restrict__ A_x,
            const float* __restrict__ W_shared,
            const float* __restrict__ W_exp,
            float* __restrict__ out,
            int T, int zoff) {
    constexpr int K = (STAGE == 1) ? D_MODEL : HID;
    constexpr int N = (STAGE == 1) ? HID : D_MODEL;
    const int s = blockIdx.z + zoff;
    const int count = (s == 0) ? T : g_counts[s - 1];
    const int m0 = blockIdx.y * 128;
    if (m0 >= count) return;
    const int n0 = blockIdx.x * 128;
    const size_t rowbase = (size_t)s * T_MAX;
    const float* __restrict__ Bw =
        (s == 0) ? W_shared : (W_exp + (size_t)(s - 1) * K * N);

    __shared__ float As[16][128];
    __shared__ float Bs[16][128];
    __shared__ int   stok[128];

    const int tid = threadIdx.x;
    if (STAGE == 1) {
        for (int i = tid; i < 128; i += 256) {
            int m = m0 + i;
            stok[i] = (m < count) ? g_tok[rowbase + m] : -1;
        }
        __syncthreads();
    }
    const int lrow = tid >> 2;
    const int lk   = (tid & 3) * 4;
    const int ty   = tid >> 4, tx = tid & 15;

    float acc[8][8] = {};

    for (int kt = 0; kt < K; kt += 16) {
#pragma unroll
        for (int h = 0; h < 2; h++) {
            int row = lrow + h * 64;
            float4 av = make_float4(0.f, 0.f, 0.f, 0.f);
            if (STAGE == 1) {
                int t = stok[row];
                if (t >= 0)
                    av = *(const float4*)(A_x + (size_t)t * D_MODEL + kt + lk);
            } else {
                if (m0 + row < count)
                    av = *(const float4*)(g_H + (rowbase + m0 + row) * (size_t)HID + kt + lk);
            }
            As[lk + 0][row] = av.x; As[lk + 1][row] = av.y;
            As[lk + 2][row] = av.z; As[lk + 3][row] = av.w;
            float4 bv = *(const float4*)(Bw + (size_t)(n0 + row) * K + kt + lk);
            Bs[lk + 0][row] = bv.x; Bs[lk + 1][row] = bv.y;
            Bs[lk + 2][row] = bv.z; Bs[lk + 3][row] = bv.w;
        }
        __syncthreads();
#pragma unroll
        for (int kk = 0; kk < 16; kk++) {
            float a[8], b[8];
            *(float4*)(a)     = *(const float4*)&As[kk][ty * 8];
            *(float4*)(a + 4) = *(const float4*)&As[kk][ty * 8 + 4];
            *(float4*)(b)     = *(const float4*)&Bs[kk][tx * 8];
            *(float4*)(b + 4) = *(const float4*)&Bs[kk][tx * 8 + 4];
#pragma unroll
            for (int i = 0; i < 8; i++)
#pragma unroll
                for (int j = 0; j < 8; j++)
                    acc[i][j] = fmaf(a[i], b[j], acc[i][j]);
        }
        __syncthreads();
    }

#pragma unroll
    for (int i = 0; i < 8; i++) {
        int m = m0 + ty * 8 + i;
        if (m >= count) continue;
        size_t r = rowbase + m;
        if (STAGE == 1) {
            float* hp = g_H + r * (size_t)HID + n0 + tx * 8;
            float v[8];
#pragma unroll
            for (int j = 0; j < 8; j++) {
                float u = acc[i][j];
                v[j] = u / (1.f + __expf(-u));   // silu
            }
            *(float4*)(hp)     = make_float4(v[0], v[1], v[2], v[3]);
            *(float4*)(hp + 4) = make_float4(v[4], v[5], v[6], v[7]);
        } else {
            int   t = g_tok[r];
            float g = g_rowgate[r];
            float* op;
            if (OUTMODE == 0) {
                op = out + (size_t)t * D_MODEL + n0 + tx * 8;
            } else {
                int sl = g_rowslot[r];
                op = g_slotbuf + ((size_t)sl * T_MAX + (size_t)t) * D_MODEL + n0 + tx * 8;
            }
            float v[8];
#pragma unroll
            for (int j = 0; j < 8; j++) v[j] = g * acc[i][j];
            *(float4*)(op)     = make_float4(v[0], v[1], v[2], v[3]);
            *(float4*)(op + 4) = make_float4(v[4], v[5], v[6], v[7]);
        }
    }
}

// ---------------- final combine: out += slot0 + slot1 ----------------------
__global__ void combine_kernel(float* __restrict__ out, int T) {
    size_t n = (size_t)T * D_MODEL;
    size_t stride = (size_t)gridDim.x * blockDim.x;
    for (size_t i = (size_t)blockIdx.x * blockDim.x + threadIdx.x; i < n; i += stride)
        out[i] += g_slotbuf[i] + g_slotbuf[(size_t)T_MAX * D_MODEL + i];
}

// ---------------- launch ----------------------------------------------------
extern "C" void kernel_launch(void* const* d_in, const int* in_sizes, int n_in,
                              void* d_out, int out_size) {
    const float* x   = (const float*)d_in[0];
    const float* sw1 = (const float*)d_in[1];
    const float* sw2 = (const float*)d_in[2];
    const float* ew1 = (const float*)d_in[3];
    const float* ew2 = (const float*)d_in[4];
    const float* gw  = (const float*)d_in[5];
    float* out = (float*)d_out;
    int T = in_sizes[0] / D_MODEL;   // 4096 for B=2, S=2048

    gate_kernel<<<(T + 7) / 8, 256>>>(x, gw, T);
    route_kernel<<<NE + 1, 256>>>(T);

    // Stage 1: all 9 segments (shared + 8 experts); empty tiles early-exit.
    {
        dim3 g(HID / 128, (T_MAX + 127) / 128, NE + 1);
        gemm_kernel<1, 0><<<g, 256>>>(x, sw1, ew1, nullptr, T, 0);
    }
    // Stage 2 shared: writes every out element with '='.
    {
        dim3 g(D_MODEL / 128, (T + 127) / 128, 1);
        gemm_kernel<2, 0><<<g, 256>>>(x, sw2, ew2, out, T, 0);
    }
    // Stage 2 experts: race-free writes into per-slot buffers.
    {
        dim3 g(D_MODEL / 128, (T_MAX + 127) / 128, NE);
        gemm_kernel<2, 1><<<g, 256>>>(x, sw2, ew2, nullptr, T, 1);
    }
    combine_kernel<<<512, 256>>>(out, T);
}

// round 3
// speedup vs baseline: 4.7531x; 4.7531x over previous
#include <cuda_runtime.h>
#include <math.h>
#include <stdint.h>

#define T_MAX   4096
#define D_MODEL 1024
#define HID     4096
#define NE      8

#define BM   128
#define BN   128
#define BK   32          // floats of K per mainloop iter
#define NSTG 3           // cp.async pipeline stages

// ---------------- device scratch (static: no allocations) ----------------
__device__ float         g_Xr[(size_t)T_MAX * D_MODEL];             // tf32-rounded x
__device__ float         g_W1[(size_t)(NE + 1) * HID * D_MODEL];    // tf32-rounded w1 (seg0=shared)
__device__ float         g_W2[(size_t)(NE + 1) * D_MODEL * HID];    // tf32-rounded w2
__device__ float         g_H [(size_t)(NE + 1) * T_MAX * HID];      // silu hidden (tf32-rounded)
__device__ float         g_slotbuf[(size_t)2 * T_MAX * D_MODEL];
__device__ float         g_gates[T_MAX * 2];
__device__ int           g_topk [T_MAX * 2];
__device__ int           g_counts[NE];
__device__ int           g_tok   [(NE + 1) * T_MAX];
__device__ float         g_rowgate[(NE + 1) * T_MAX];
__device__ unsigned char g_rowslot[(NE + 1) * T_MAX];

// ---------------- PTX helpers (plain-target only: no tcgen05) -------------
__device__ __forceinline__ uint32_t smem_u32(const void* p) {
    uint32_t a;
    asm("{ .reg .u64 t; cvta.to.shared.u64 t, %1; cvt.u32.u64 %0, t; }" : "=r"(a) : "l"(p));
    return a;
}
__device__ __forceinline__ float rna_tf32(float x) {
    uint32_t u;
    asm("cvt.rna.tf32.f32 %0, %1;" : "=r"(u) : "f"(x));
    return __uint_as_float(u);
}
__device__ __forceinline__ void cpa16(uint32_t dst, const void* src, int zf) {
    asm volatile("cp.async.cg.shared.global [%0], [%1], 16, %2;\n"
                 :: "r"(dst), "l"(src), "r"(zf) : "memory");
}
__device__ __forceinline__ void cpa_commit() {
    asm volatile("cp.async.commit_group;\n" ::: "memory");
}

// smem: A [NSTG][4096]f, B [NSTG][4096]f, stok[128]i
#define SMEM_FLOATS (2 * NSTG * BM * BK)
#define SMEM_BYTES  ((SMEM_FLOATS + 128) * 4)

// ---------------- prep: tf32 RNA rounding copies ----------------
__global__ void round_tf32_kernel(float4* __restrict__ dst, const float4* __restrict__ src, int n4) {
    int stride = gridDim.x * blockDim.x;
    for (int i = blockIdx.x * blockDim.x + threadIdx.x; i < n4; i += stride) {
        float4 v = src[i];
        v.x = rna_tf32(v.x); v.y = rna_tf32(v.y);
        v.z = rna_tf32(v.z); v.w = rna_tf32(v.w);
        dst[i] = v;
    }
}

// ---------------- gating ----------------
__global__ void gate_kernel(const float* __restrict__ x, const float* __restrict__ gw, int T) {
    int warp = (blockIdx.x * blockDim.x + threadIdx.x) >> 5;
    int lane = threadIdx.x & 31;
    if (warp >= T) return;
    const float* xr = x + (size_t)warp * D_MODEL;
    float logit[NE];
#pragma unroll
    for (int e = 0; e < NE; e++) {
        float s = 0.f;
        for (int k = lane; k < D_MODEL; k += 32)
            s = fmaf(xr[k], gw[e * D_MODEL + k], s);
#pragma unroll
        for (int o = 16; o; o >>= 1) s += __shfl_xor_sync(0xffffffffu, s, o);
        logit[e] = s;
    }
    if (lane == 0) {
        int i0 = 0; float v0 = logit[0];
#pragma unroll
        for (int e = 1; e < NE; e++) if (logit[e] > v0) { v0 = logit[e]; i0 = e; }
        int i1 = -1; float v1 = -1e30f;
#pragma unroll
        for (int e = 0; e < NE; e++) if (e != i0 && logit[e] > v1) { v1 = logit[e]; i1 = e; }
        float e1 = expf(v1 - v0);
        float inv = 1.f / (1.f + e1);
        g_topk [2 * warp] = i0;  g_topk [2 * warp + 1] = i1;
        g_gates[2 * warp] = inv; g_gates[2 * warp + 1] = e1 * inv;
    }
}

// ---------------- routing (deterministic prefix scan) ----------------
__global__ void route_kernel(int T) {
    int e = blockIdx.x, tid = threadIdx.x, lane = tid & 31, wid = tid >> 5;
    if (e == NE) {
        for (int i = tid; i < T; i += blockDim.x) {
            g_tok[i] = i; g_rowgate[i] = 1.f; g_rowslot[i] = 0;
        }
        return;
    }
    __shared__ int wsum[8], wpre[8], s_total;
    int base = 0;
    for (int t0 = 0; t0 < T; t0 += 256) {
        int t = t0 + tid, slot = -1;
        if (t < T) {
            if      (g_topk[2 * t]     == e) slot = 0;
            else if (g_topk[2 * t + 1] == e) slot = 1;
        }
        unsigned m = __ballot_sync(0xffffffffu, slot >= 0);
        int pre = __popc(m & ((1u << lane) - 1u));
        if (lane == 0) wsum[wid] = __popc(m);
        __syncthreads();
        if (tid == 0) {
            int a = 0;
            for (int w = 0; w < 8; w++) { wpre[w] = a; a += wsum[w]; }
            s_total = a;
        }
        __syncthreads();
        if (slot >= 0) {
            int pos = base + wpre[wid] + pre;
            size_t r = (size_t)(e + 1) * T_MAX + pos;
            g_tok[r] = t; g_rowgate[r] = g_gates[2 * t + slot];
            g_rowslot[r] = (unsigned char)slot;
        }
        base += s_total;
        __syncthreads();
    }
    if (tid == 0) g_counts[e] = base;
}

// ---------------- tf32 mma.sync GEMM (plain-target tensor cores) ----------
// 128x128 block, 4 warps (2x2) of 64x64, BK=32, 3-stage cp.async pipeline.
// STAGE1: H = rna(silu(X @ W1^T)); STAGE2: Y = H @ W2^T (gated output).
template <int STAGE, int OUTMODE>
__global__ void __launch_bounds__(128, 2)
gemm_mma(float* __restrict__ out, int T, int zoff) {
    constexpr int K     = (STAGE == 1) ? D_MODEL : HID;
    constexpr int NITER = K / BK;

    const int s = blockIdx.z + zoff;
    const int count = (s == 0) ? T : g_counts[s - 1];
    const int m0 = blockIdx.y * BM;
    if (m0 >= count) return;
    const int n0 = blockIdx.x * BN;
    const size_t rowbase = (size_t)s * T_MAX;
    const float* __restrict__ Bw =
        ((STAGE == 1) ? g_W1 : g_W2) + (size_t)s * K * ((STAGE == 1) ? HID : D_MODEL);
    const float* __restrict__ Ah = g_H + (rowbase + m0) * (size_t)HID;

    extern __shared__ float smem[];
    float* As = smem;                       // [NSTG][4][128][8]
    float* Bs = smem + NSTG * BM * BK;      // [NSTG][4][128][8]
    int*   stok = (int*)(smem + SMEM_FLOATS);

    const int tid = threadIdx.x;
    if (STAGE == 1) {
        for (int i = tid; i < BM; i += 128) {
            int m = m0 + i;
            stok[i] = (m < count) ? g_tok[rowbase + m] : -1;
        }
        __syncthreads();
    }
    const uint32_t sA = smem_u32(As), sB = smem_u32(Bs);

    // fill one pipeline buffer: A and B tiles, fragment-friendly layout
    // smem offset for gmem chunk (row m, 16B-chunk c of 8):
    //   kstep=(c>>1), half=(c&1): off = ((kstep*128 + m)*8 + half*4) floats
    auto fill = [&](int it, int buf) {
        const int kt = it * BK;
        const uint32_t aB = sA + buf * (BM * BK * 4);
        const uint32_t bB = sB + buf * (BM * BK * 4);
#pragma unroll
        for (int i = 0; i < 8; i++) {
            int cid = i * 128 + tid;
            int m = cid >> 3, c = cid & 7;
            uint32_t off = ((((c >> 1) * 128 + m) * 8 + (c & 1) * 4)) * 4;
            const float* srcA; int zf = 16;
            if (STAGE == 1) {
                int t = stok[m];
                srcA = g_Xr + (size_t)((t < 0) ? 0 : t) * D_MODEL + kt + c * 4;
                if (t < 0) zf = 0;
            } else {
                int mg = m0 + m;
                srcA = Ah + (size_t)((mg < count) ? m : 0) * HID + kt + c * 4;
                if (mg >= count) zf = 0;
            }
            cpa16(aB + off, srcA, zf);
            cpa16(bB + off, Bw + (size_t)(n0 + m) * K + kt + c * 4, 16);
        }
        cpa_commit();
    };

    const int lane = tid & 31, wid = tid >> 5;
    const int g = lane >> 2, t4 = lane & 3;
    const int warpM = (wid & 1) * 64, warpN = (wid >> 1) * 64;

    float acc[4][8][4];
#pragma unroll
    for (int a = 0; a < 4; a++)
#pragma unroll
        for (int b = 0; b < 8; b++)
#pragma unroll
            for (int c = 0; c < 4; c++) acc[a][b][c] = 0.f;

    fill(0, 0);
    fill(1, 1);

    for (int it = 0; it < NITER; it++) {
        const int buf = it % NSTG;
        asm volatile("cp.async.wait_group 1;" ::: "memory");
        __syncthreads();                        // data ready + all warps done with buf we refill
        if (it + 2 < NITER) fill(it + 2, (it + 2) % NSTG);

        const float* Ab = As + buf * (BM * BK);
        const float* Bb = Bs + buf * (BM * BK);
#pragma unroll
        for (int ks = 0; ks < 4; ks++) {
            uint32_t af[4][4], bf[8][2];
#pragma unroll
            for (int mt = 0; mt < 4; mt++) {
                const float* p = Ab + (ks * 128 + warpM + mt * 16 + g) * 8;
                af[mt][0] = __float_as_uint(p[t4]);
                af[mt][1] = __float_as_uint(p[64 + t4]);      // +8 rows
                af[mt][2] = __float_as_uint(p[t4 + 4]);
                af[mt][3] = __float_as_uint(p[64 + t4 + 4]);
            }
#pragma unroll
            for (int nt = 0; nt < 8; nt++) {
                const float* p = Bb + (ks * 128 + warpN + nt * 8 + g) * 8;
                bf[nt][0] = __float_as_uint(p[t4]);
                bf[nt][1] = __float_as_uint(p[t4 + 4]);
            }
#pragma unroll
            for (int mt = 0; mt < 4; mt++)
#pragma unroll
                for (int nt = 0; nt < 8; nt++)
                    asm volatile(
                        "mma.sync.aligned.m16n8k8.row.col.f32.tf32.tf32.f32 "
                        "{%0,%1,%2,%3}, {%4,%5,%6,%7}, {%8,%9}, {%0,%1,%2,%3};"
                        : "+f"(acc[mt][nt][0]), "+f"(acc[mt][nt][1]),
                          "+f"(acc[mt][nt][2]), "+f"(acc[mt][nt][3])
                        : "r"(af[mt][0]), "r"(af[mt][1]), "r"(af[mt][2]), "r"(af[mt][3]),
                          "r"(bf[nt][0]), "r"(bf[nt][1]));
        }
    }

    // ---- epilogue: c0,c1 -> (row g, cols 2t4,2t4+1); c2,c3 -> row g+8
#pragma unroll
    for (int mt = 0; mt < 4; mt++) {
#pragma unroll
        for (int half = 0; half < 2; half++) {
            int m = m0 + warpM + mt * 16 + g + half * 8;
            if (m >= count) continue;
            size_t r = rowbase + m;
            if (STAGE == 1) {
                float* hp = g_H + r * (size_t)HID + n0 + warpN + 2 * t4;
#pragma unroll
                for (int nt = 0; nt < 8; nt++) {
                    float v0 = acc[mt][nt][half * 2 + 0];
                    float v1 = acc[mt][nt][half * 2 + 1];
                    v0 = rna_tf32(v0 / (1.f + __expf(-v0)));
                    v1 = rna_tf32(v1 / (1.f + __expf(-v1)));
                    *(float2*)(hp + nt * 8) = make_float2(v0, v1);
                }
            } else {
                int   t  = g_tok[r];
                float gv = g_rowgate[r];
                float* op;
                if (OUTMODE == 0)
                    op = out + (size_t)t * D_MODEL + n0 + warpN + 2 * t4;
                else {
                    int sl = g_rowslot[r];
                    op = g_slotbuf + ((size_t)sl * T_MAX + (size_t)t) * D_MODEL
                       + n0 + warpN + 2 * t4;
                }
#pragma unroll
                for (int nt = 0; nt < 8; nt++)
                    *(float2*)(op + nt * 8) =
                        make_float2(gv * acc[mt][nt][half * 2 + 0],
                                    gv * acc[mt][nt][half * 2 + 1]);
            }
        }
    }
}

// ---------------- combine ----------------
__global__ void combine_kernel(float* __restrict__ out, int T) {
    size_t n = (size_t)T * D_MODEL;
    size_t stride = (size_t)gridDim.x * blockDim.x;
    for (size_t i = (size_t)blockIdx.x * blockDim.x + threadIdx.x; i < n; i += stride)
        out[i] += g_slotbuf[i] + g_slotbuf[(size_t)T_MAX * D_MODEL + i];
}

// ---------------- launch ----------------
extern "C" void kernel_launch(void* const* d_in, const int* in_sizes, int n_in,
                              void* d_out, int out_size) {
    const float* x   = (const float*)d_in[0];
    const float* sw1 = (const float*)d_in[1];
    const float* sw2 = (const float*)d_in[2];
    const float* ew1 = (const float*)d_in[3];
    const float* ew2 = (const float*)d_in[4];
    const float* gw  = (const float*)d_in[5];
    float* out = (float*)d_out;
    int T = in_sizes[0] / D_MODEL;

    cudaFuncSetAttribute(gemm_mma<1, 0>, cudaFuncAttributeMaxDynamicSharedMemorySize, SMEM_BYTES);
    cudaFuncSetAttribute(gemm_mma<2, 0>, cudaFuncAttributeMaxDynamicSharedMemorySize, SMEM_BYTES);
    cudaFuncSetAttribute(gemm_mma<2, 1>, cudaFuncAttributeMaxDynamicSharedMemorySize, SMEM_BYTES);

    float *d_Xr, *d_W1, *d_W2;
    cudaGetSymbolAddress((void**)&d_Xr, g_Xr);
    cudaGetSymbolAddress((void**)&d_W1, g_W1);
    cudaGetSymbolAddress((void**)&d_W2, g_W2);

    // tf32 RNA pre-rounding (kills tf32 truncation bias)
    round_tf32_kernel<<<1024, 256>>>((float4*)d_Xr, (const float4*)x, T * D_MODEL / 4);
    round_tf32_kernel<<<1024, 256>>>((float4*)d_W1, (const float4*)sw1, HID * D_MODEL / 4);
    round_tf32_kernel<<<2048, 256>>>((float4*)(d_W1 + (size_t)HID * D_MODEL),
                                     (const float4*)ew1, NE * HID * D_MODEL / 4);
    round_tf32_kernel<<<1024, 256>>>((float4*)d_W2, (const float4*)sw2, D_MODEL * HID / 4);
    round_tf32_kernel<<<2048, 256>>>((float4*)(d_W2 + (size_t)D_MODEL * HID),
                                     (const float4*)ew2, NE * D_MODEL * HID / 4);

    gate_kernel<<<(T + 7) / 8, 256>>>(x, gw, T);
    route_kernel<<<NE + 1, 256>>>(T);

    {   // stage 1: all 9 segments (empty m-tiles early-exit)
        dim3 g(HID / BN, T_MAX / BM, NE + 1);
        gemm_mma<1, 0><<<g, 128, SMEM_BYTES>>>(nullptr, T, 0);
    }
    {   // stage 2 shared -> out (writes '=', every element)
        dim3 g(D_MODEL / BN, T_MAX / BM, 1);
        gemm_mma<2, 0><<<g, 128, SMEM_BYTES>>>(out, T, 0);
    }
    {   // stage 2 experts -> per-slot buffers (race-free)
        dim3 g(D_MODEL / BN, T_MAX / BM, NE);
        gemm_mma<2, 1><<<g, 128, SMEM_BYTES>>>(nullptr, T, 1);
    }
    combine_kernel<<<512, 256>>>(out, T);
}

// round 6
// speedup vs baseline: 12.0141x; 2.5276x over previous
#include <cuda_runtime.h>
#include <cuda_fp16.h>
#include <math.h>
#include <stdint.h>

#define T_MAX   4096
#define D_MODEL 1024
#define HID     4096
#define NE      8

#define BM   128
#define BN   128
#define BKH  32          // k-halves per mainloop iter (64B per row)
#define NSTG 3

// ---------------- device scratch (static: no allocations) ----------------
__device__ __half        g_Xh[(size_t)T_MAX * D_MODEL];
__device__ __half        g_W1h[(size_t)(NE + 1) * HID * D_MODEL];
__device__ __half        g_W2h[(size_t)(NE + 1) * D_MODEL * HID];
__device__ __half        g_Hh[(size_t)(NE + 1) * T_MAX * HID];
__device__ float         g_slotbuf[(size_t)2 * T_MAX * D_MODEL];
__device__ float         g_gates[T_MAX * 2];
__device__ int           g_topk [T_MAX * 2];
__device__ int           g_counts[NE];
__device__ int           g_tok   [(NE + 1) * T_MAX];
__device__ float         g_rowgate[(NE + 1) * T_MAX];
__device__ unsigned char g_rowslot[(NE + 1) * T_MAX];

// ---------------- PTX helpers ----------------
__device__ __forceinline__ uint32_t smem_u32(const void* p) {
    uint32_t a;
    asm("{ .reg .u64 t; cvta.to.shared.u64 t, %1; cvt.u32.u64 %0, t; }" : "=r"(a) : "l"(p));
    return a;
}
__device__ __forceinline__ void cpa16(uint32_t dst, const void* src, int zf) {
    asm volatile("cp.async.cg.shared.global [%0], [%1], 16, %2;\n"
                 :: "r"(dst), "l"(src), "r"(zf) : "memory");
}
__device__ __forceinline__ void cpa_commit() {
    asm volatile("cp.async.commit_group;\n" ::: "memory");
}
#define LDSM4(r0, r1, r2, r3, addr) \
    asm volatile("ldmatrix.sync.aligned.m8n8.x4.shared.b16 {%0,%1,%2,%3}, [%4];" \
        : "=r"(r0), "=r"(r1), "=r"(r2), "=r"(r3) : "r"(addr))

// per-stage: A 8KB + B 8KB
#define STG_BYTES 16384
#define SMEM_BYTES (NSTG * STG_BYTES + 512)

// ---------------- prep: fp32 -> fp16 (RNE) ----------------
__global__ void to_half_kernel(uint2* __restrict__ dst, const float4* __restrict__ src, int n4) {
    int stride = gridDim.x * blockDim.x;
    for (int i = blockIdx.x * blockDim.x + threadIdx.x; i < n4; i += stride) {
        float4 v = src[i];
        __half2 lo = __floats2half2_rn(v.x, v.y);
        __half2 hi = __floats2half2_rn(v.z, v.w);
        uint2 o;
        o.x = *(uint32_t*)&lo; o.y = *(uint32_t*)&hi;
        dst[i] = o;
    }
}

// ---------------- gating ----------------
__global__ void gate_kernel(const float* __restrict__ x, const float* __restrict__ gw, int T) {
    int warp = (blockIdx.x * blockDim.x + threadIdx.x) >> 5;
    int lane = threadIdx.x & 31;
    if (warp >= T) return;
    const float* xr = x + (size_t)warp * D_MODEL;
    float logit[NE];
#pragma unroll
    for (int e = 0; e < NE; e++) {
        float s = 0.f;
        for (int k = lane; k < D_MODEL; k += 32)
            s = fmaf(xr[k], gw[e * D_MODEL + k], s);
#pragma unroll
        for (int o = 16; o; o >>= 1) s += __shfl_xor_sync(0xffffffffu, s, o);
        logit[e] = s;
    }
    if (lane == 0) {
        int i0 = 0; float v0 = logit[0];
#pragma unroll
        for (int e = 1; e < NE; e++) if (logit[e] > v0) { v0 = logit[e]; i0 = e; }
        int i1 = -1; float v1 = -1e30f;
#pragma unroll
        for (int e = 0; e < NE; e++) if (e != i0 && logit[e] > v1) { v1 = logit[e]; i1 = e; }
        float e1 = expf(v1 - v0);
        float inv = 1.f / (1.f + e1);
        g_topk [2 * warp] = i0;  g_topk [2 * warp + 1] = i1;
        g_gates[2 * warp] = inv; g_gates[2 * warp + 1] = e1 * inv;
    }
}

// ---------------- routing (deterministic prefix scan) ----------------
__global__ void route_kernel(int T) {
    int e = blockIdx.x, tid = threadIdx.x, lane = tid & 31, wid = tid >> 5;
    if (e == NE) {
        for (int i = tid; i < T; i += blockDim.x) {
            g_tok[i] = i; g_rowgate[i] = 1.f; g_rowslot[i] = 0;
        }
        return;
    }
    __shared__ int wsum[8], wpre[8], s_total;
    int base = 0;
    for (int t0 = 0; t0 < T; t0 += 256) {
        int t = t0 + tid, slot = -1;
        if (t < T) {
            if      (g_topk[2 * t]     == e) slot = 0;
            else if (g_topk[2 * t + 1] == e) slot = 1;
        }
        unsigned m = __ballot_sync(0xffffffffu, slot >= 0);
        int pre = __popc(m & ((1u << lane) - 1u));
        if (lane == 0) wsum[wid] = __popc(m);
        __syncthreads();
        if (tid == 0) {
            int a = 0;
            for (int w = 0; w < 8; w++) { wpre[w] = a; a += wsum[w]; }
            s_total = a;
        }
        __syncthreads();
        if (slot >= 0) {
            int pos = base + wpre[wid] + pre;
            size_t r = (size_t)(e + 1) * T_MAX + pos;
            g_tok[r] = t; g_rowgate[r] = g_gates[2 * t + slot];
            g_rowslot[r] = (unsigned char)slot;
        }
        base += s_total;
        __syncthreads();
    }
    if (tid == 0) g_counts[e] = base;
}

// ---------------- fp16 mma.sync GEMM ----------------
// 128x128 block, 4 warps (2x2) of 64x64, BKH=32 halves/iter, 3-stage cp.async.
// smem tile layout: logical row m (64B = 4 x 16B atoms) packed 2 rows per 128B
// physical row; atom position swizzled: a' = a ^ (prow & 7). Conflict-free for
// ldmatrix lane patterns (verified for all alignments).
// STAGE1: H = fp16(silu(X @ W1^T)); STAGE2: Y = H @ W2^T (gated).
template <int STAGE, int OUTMODE>
__global__ void __launch_bounds__(128, 2)
gemm_mma(float* __restrict__ out, int T, int zoff) {
    constexpr int K     = (STAGE == 1) ? D_MODEL : HID;   // in halves/elements
    constexpr int NITER = K / BKH;

    const int s = blockIdx.z + zoff;
    const int count = (s == 0) ? T : g_counts[s - 1];
    const int m0 = blockIdx.y * BM;
    if (m0 >= count) return;
    const int n0 = blockIdx.x * BN;
    const size_t rowbase = (size_t)s * T_MAX;
    const __half* __restrict__ Bw =
        ((STAGE == 1) ? g_W1h : g_W2h) + (size_t)s * K * ((STAGE == 1) ? HID : D_MODEL);
    const __half* __restrict__ Ah = g_Hh + (rowbase + m0) * (size_t)HID;

    extern __shared__ char smem[];
    const uint32_t smb = smem_u32(smem);
    int* stok = (int*)(smem + NSTG * STG_BYTES);

    const int tid = threadIdx.x;
    if (STAGE == 1) {
        for (int i = tid; i < BM; i += 128) {
            int m = m0 + i;
            stok[i] = (m < count) ? g_tok[rowbase + m] : -1;
        }
        __syncthreads();
    }

    // fill buffer buf with k-halves [it*BKH, it*BKH+32): 8 cp.async/thread
    auto fill = [&](int it, int buf) {
        const int kt = it * BKH;
        const uint32_t aB = smb + buf * STG_BYTES;
        const uint32_t bB = aB + 8192;
#pragma unroll
        for (int i = 0; i < 4; i++) {
            int cid = i * 128 + tid;
            int m = cid >> 2, c = cid & 3;
            int prow = m >> 1;
            uint32_t off = prow * 128 + ((((m & 1) * 4 + c) ^ (prow & 7)) << 4);
            // A chunk
            const __half* srcA; int zf = 16;
            if (STAGE == 1) {
                int t = stok[m];
                srcA = g_Xh + (size_t)((t < 0) ? 0 : t) * D_MODEL + kt + c * 8;
                if (t < 0) zf = 0;
            } else {
                int mg = m0 + m;
                srcA = Ah + (size_t)((mg < count) ? m : 0) * HID + kt + c * 8;
                if (mg >= count) zf = 0;
            }
            cpa16(aB + off, srcA, zf);
            // B chunk
            cpa16(bB + off, Bw + (size_t)(n0 + m) * K + kt + c * 8, 16);
        }
        cpa_commit();
    };

    const int lane = tid & 31, wid = tid >> 5;
    const int g = lane >> 2, t4 = lane & 3;
    const int warpM = (wid & 1) * 64, warpN = (wid >> 1) * 64;

    // per-lane ldmatrix base offsets (mt=0 / np=0, ks=0, stage 0)
    uint32_t aoff, boff;
    {
        int ar = lane & 15, asel = lane >> 4;       // A: row, atom
        int m = warpM + ar, prow = m >> 1;
        int a = (m & 1) * 4 + asel;
        aoff = prow * 128 + ((a ^ (prow & 7)) << 4);
        int br = ((lane >> 4) << 3) + (lane & 7);   // B: row
        int bsel = (lane >> 3) & 1;                 // B: atom
        int n = warpN + br, prow2 = n >> 1;
        int ab = (n & 1) * 4 + bsel;
        boff = 8192 + prow2 * 128 + ((ab ^ (prow2 & 7)) << 4);
    }

    float acc[4][8][4];
#pragma unroll
    for (int a = 0; a < 4; a++)
#pragma unroll
        for (int b = 0; b < 8; b++)
#pragma unroll
            for (int c = 0; c < 4; c++) acc[a][b][c] = 0.f;

    fill(0, 0);
    fill(1, 1);

    for (int it = 0; it < NITER; it++) {
        const int buf = it % NSTG;
        asm volatile("cp.async.wait_group 1;" ::: "memory");
        __syncthreads();
        if (it + 2 < NITER) fill(it + 2, (it + 2) % NSTG);

        const uint32_t Ab = smb + buf * STG_BYTES + aoff;
        const uint32_t Bb = smb + buf * STG_BYTES + boff;
#pragma unroll
        for (int ks = 0; ks < 2; ks++) {
            uint32_t af[4][4], bf[4][4];
#pragma unroll
            for (int mt = 0; mt < 4; mt++)
                LDSM4(af[mt][0], af[mt][1], af[mt][2], af[mt][3],
                      (Ab + mt * 1024) ^ (ks * 32));
#pragma unroll
            for (int np = 0; np < 4; np++)
                LDSM4(bf[np][0], bf[np][1], bf[np][2], bf[np][3],
                      (Bb + np * 1024) ^ (ks * 32));
#pragma unroll
            for (int mt = 0; mt < 4; mt++)
#pragma unroll
                for (int nt = 0; nt < 8; nt++)
                    asm volatile(
                        "mma.sync.aligned.m16n8k16.row.col.f32.f16.f16.f32 "
                        "{%0,%1,%2,%3}, {%4,%5,%6,%7}, {%8,%9}, {%0,%1,%2,%3};"
                        : "+f"(acc[mt][nt][0]), "+f"(acc[mt][nt][1]),
                          "+f"(acc[mt][nt][2]), "+f"(acc[mt][nt][3])
                        : "r"(af[mt][0]), "r"(af[mt][1]), "r"(af[mt][2]), "r"(af[mt][3]),
                          "r"(bf[nt >> 1][(nt & 1) * 2]), "r"(bf[nt >> 1][(nt & 1) * 2 + 1]));
        }
    }

    // ---- epilogue: c0,c1 -> (row g, cols 2t4,2t4+1); c2,c3 -> row g+8
#pragma unroll
    for (int mt = 0; mt < 4; mt++) {
#pragma unroll
        for (int half = 0; half < 2; half++) {
            int m = m0 + warpM + mt * 16 + g + half * 8;
            if (m >= count) continue;
            size_t r = rowbase + m;
            if (STAGE == 1) {
                __half* hp = g_Hh + r * (size_t)HID + n0 + warpN + 2 * t4;
#pragma unroll
                for (int nt = 0; nt < 8; nt++) {
                    float v0 = acc[mt][nt][half * 2 + 0];
                    float v1 = acc[mt][nt][half * 2 + 1];
                    v0 = v0 / (1.f + __expf(-v0));
                    v1 = v1 / (1.f + __expf(-v1));
                    *(__half2*)(hp + nt * 8) = __floats2half2_rn(v0, v1);
                }
            } else {
                int   t  = g_tok[r];
                float gv = g_rowgate[r];
                float* op;
                if (OUTMODE == 0)
                    op = out + (size_t)t * D_MODEL + n0 + warpN + 2 * t4;
                else {
                    int sl = g_rowslot[r];
                    op = g_slotbuf + ((size_t)sl * T_MAX + (size_t)t) * D_MODEL
                       + n0 + warpN + 2 * t4;
                }
#pragma unroll
                for (int nt = 0; nt < 8; nt++)
                    *(float2*)(op + nt * 8) =
                        make_float2(gv * acc[mt][nt][half * 2 + 0],
                                    gv * acc[mt][nt][half * 2 + 1]);
            }
        }
    }
}

// ---------------- combine ----------------
__global__ void combine_kernel(float* __restrict__ out, int T) {
    size_t n = (size_t)T * D_MODEL;
    size_t stride = (size_t)gridDim.x * blockDim.x;
    for (size_t i = (size_t)blockIdx.x * blockDim.x + threadIdx.x; i < n; i += stride)
        out[i] += g_slotbuf[i] + g_slotbuf[(size_t)T_MAX * D_MODEL + i];
}

// ---------------- launch ----------------
extern "C" void kernel_launch(void* const* d_in, const int* in_sizes, int n_in,
                              void* d_out, int out_size) {
    const float* x   = (const float*)d_in[0];
    const float* sw1 = (const float*)d_in[1];
    const float* sw2 = (const float*)d_in[2];
    const float* ew1 = (const float*)d_in[3];
    const float* ew2 = (const float*)d_in[4];
    const float* gw  = (const float*)d_in[5];
    float* out = (float*)d_out;
    int T = in_sizes[0] / D_MODEL;

    cudaFuncSetAttribute(gemm_mma<1, 0>, cudaFuncAttributeMaxDynamicSharedMemorySize, SMEM_BYTES);
    cudaFuncSetAttribute(gemm_mma<2, 0>, cudaFuncAttributeMaxDynamicSharedMemorySize, SMEM_BYTES);
    cudaFuncSetAttribute(gemm_mma<2, 1>, cudaFuncAttributeMaxDynamicSharedMemorySize, SMEM_BYTES);

    __half *d_Xh, *d_W1h, *d_W2h;
    cudaGetSymbolAddress((void**)&d_Xh, g_Xh);
    cudaGetSymbolAddress((void**)&d_W1h, g_W1h);
    cudaGetSymbolAddress((void**)&d_W2h, g_W2h);

    // fp32 -> fp16 RNE conversion (unbiased; eps 2^-11 same as tf32)
    to_half_kernel<<<1024, 256>>>((uint2*)d_Xh, (const float4*)x, T * D_MODEL / 4);
    to_half_kernel<<<1024, 256>>>((uint2*)d_W1h, (const float4*)sw1, HID * D_MODEL / 4);
    to_half_kernel<<<4096, 256>>>((uint2*)(d_W1h + (size_t)HID * D_MODEL),
                                  (const float4*)ew1, NE * HID * D_MODEL / 4);
    to_half_kernel<<<1024, 256>>>((uint2*)d_W2h, (const float4*)sw2, D_MODEL * HID / 4);
    to_half_kernel<<<4096, 256>>>((uint2*)(d_W2h + (size_t)D_MODEL * HID),
                                  (const float4*)ew2, NE * D_MODEL * HID / 4);

    gate_kernel<<<(T + 7) / 8, 256>>>(x, gw, T);
    route_kernel<<<NE + 1, 256>>>(T);

    {   // stage 1: all 9 segments (empty m-tiles early-exit)
        dim3 g(HID / BN, T_MAX / BM, NE + 1);
        gemm_mma<1, 0><<<g, 128, SMEM_BYTES>>>(nullptr, T, 0);
    }
    {   // stage 2 shared -> out ('=' writes every element)
        dim3 g(D_MODEL / BN, T_MAX / BM, 1);
        gemm_mma<2, 0><<<g, 128, SMEM_BYTES>>>(out, T, 0);
    }
    {   // stage 2 experts -> per-slot buffers (race-free)
        dim3 g(D_MODEL / BN, T_MAX / BM, NE);
        gemm_mma<2, 1><<<g, 128, SMEM_BYTES>>>(nullptr, T, 1);
    }
    combine_kernel<<<512, 256>>>(out, T);
}